// round 1
// baseline (speedup 1.0000x reference)
#include <cuda_runtime.h>
#include <cstdint>

// Problem constants (fixed by the dataset)
#define BB    4096
#define TT    2048
#define VOCAB 300
#define HID   2
#define GG    8      // 4*HID gate width

// ---------------------------------------------------------------------------
// Activations: accurate-ish fast paths (EX2 + RCP via MUFU), ~1e-6 rel error.
// sigmoid(x) = 1 / (1 + e^-x)
// tanh(x)    = (1 - e^-2x) / (1 + e^-2x)
// Inputs here are bounded (|z| <~ 5, |c| <~ 16) so no overflow handling needed,
// but clamp defensively to keep expf in safe range.
// ---------------------------------------------------------------------------
__device__ __forceinline__ float sig_f(float x) {
    x = fminf(fmaxf(x, -30.0f), 30.0f);
    float e = __expf(-x);
    return __fdividef(1.0f, 1.0f + e);
}

__device__ __forceinline__ float tanh_f(float x) {
    x = fminf(fmaxf(x, -15.0f), 15.0f);
    float e = __expf(-2.0f * x);
    return __fdividef(1.0f - e, 1.0f + e);
}

// One thread per batch row; 32-thread blocks -> one warp per block, 128 blocks
// spread over SMs. Shared holds the per-token gate preactivation table.
__global__ void __launch_bounds__(32, 1)
lstm_seq_kernel(const int*   __restrict__ ids,
                const float* __restrict__ E,
                const float* __restrict__ W,
                const float* __restrict__ U,
                const float* __restrict__ bias,
                float*       __restrict__ out)
{
    __shared__ float Zt[VOCAB * GG];   // 300 * 8 floats = 9600 B

    const int lane = threadIdx.x;

    // Build Ztab[v][j] = E[v,0]*W[0,j] + E[v,1]*W[1,j] + b[j]
    for (int idx = lane; idx < VOCAB * GG; idx += 32) {
        int v = idx >> 3;
        int j = idx & 7;
        Zt[idx] = fmaf(E[2 * v], W[j], fmaf(E[2 * v + 1], W[GG + j], bias[j]));
    }

    // Recurrent kernel U [2, 8] into registers
    float u0[GG], u1[GG];
#pragma unroll
    for (int j = 0; j < GG; j++) { u0[j] = U[j]; u1[j] = U[GG + j]; }

    __syncthreads();

    const int row = blockIdx.x * 32 + lane;   // 0..4095
    const int4*  idp  = reinterpret_cast<const int4*>(ids + (size_t)row * TT);
    float4*      outp = reinterpret_cast<float4*>(out + (size_t)row * TT * HID);

    float h0 = 0.0f, h1 = 0.0f, c0 = 0.0f, c1 = 0.0f;

    for (int t4 = 0; t4 < TT / 4; t4++) {
        // Prefetch 4 token ids at once (16B load)
        const int4 iv = idp[t4];
        int idv[4] = { iv.x, iv.y, iv.z, iv.w };

        float hh[8];

#pragma unroll
        for (int k = 0; k < 4; k++) {
            // Gate preactivation from the table (shared, 32B-aligned)
            const float4* zp = reinterpret_cast<const float4*>(&Zt[idv[k] * GG]);
            float4 za = zp[0];
            float4 zb = zp[1];
            float z[8] = { za.x, za.y, za.z, za.w, zb.x, zb.y, zb.z, zb.w };

            // z += h @ U
#pragma unroll
            for (int j = 0; j < 8; j++)
                z[j] = fmaf(h1, u1[j], fmaf(h0, u0[j], z[j]));

            // Keras gate order: i, f, g, o (each HID=2 wide)
            float i0 = sig_f(z[0]),  i1 = sig_f(z[1]);
            float f0 = sig_f(z[2]),  f1 = sig_f(z[3]);
            float g0 = tanh_f(z[4]), g1 = tanh_f(z[5]);
            float o0 = sig_f(z[6]),  o1 = sig_f(z[7]);

            c0 = fmaf(f0, c0, i0 * g0);
            c1 = fmaf(f1, c1, i1 * g1);
            h0 = o0 * tanh_f(c0);
            h1 = o1 * tanh_f(c1);

            hh[2 * k]     = h0;
            hh[2 * k + 1] = h1;
        }

        // 4 steps * 2 floats = 8 contiguous floats -> two float4 stores
        outp[t4 * 2 + 0] = make_float4(hh[0], hh[1], hh[2], hh[3]);
        outp[t4 * 2 + 1] = make_float4(hh[4], hh[5], hh[6], hh[7]);
    }
}

extern "C" void kernel_launch(void* const* d_in, const int* in_sizes, int n_in,
                              void* d_out, int out_size)
{
    const int*   ids  = (const int*)  d_in[0];   // [B, T] int32
    const float* E    = (const float*)d_in[1];   // [300, 2]
    const float* W    = (const float*)d_in[2];   // [2, 8]
    const float* U    = (const float*)d_in[3];   // [2, 8]
    const float* bias = (const float*)d_in[4];   // [8]
    float*       out  = (float*)d_out;           // [B, T, 2]

    (void)in_sizes; (void)n_in; (void)out_size;

    lstm_seq_kernel<<<BB / 32, 32>>>(ids, E, W, U, bias, out);
}

// round 2
// speedup vs baseline: 1.0082x; 1.0082x over previous
#include <cuda_runtime.h>
#include <cstdint>

// Problem constants (fixed by the dataset)
#define BB    4096
#define TT    2048
#define VOCAB 300
#define HID   2
#define GG    8      // 4*HID gate width

// Accurate fast activations: 2 MUFU each (EX2 + RCP), ~1e-6 error.
// Inputs are provably bounded here (|z| <~ 5, |c| <~ 12): no clamps needed.
__device__ __forceinline__ float sig_f(float x) {
    float e = __expf(-x);                     // MUFU.EX2 (+1 mul)
    return __fdividef(1.0f, 1.0f + e);        // MUFU.RCP
}
__device__ __forceinline__ float tanh_f(float x) {
    float e = __expf(-2.0f * x);              // folds to 1 mul + EX2
    return __fdividef(2.0f, 1.0f + e) - 1.0f; // RCP + mul + add
}

// 2 threads per batch row: lane parity = hidden unit. Each thread computes
// its unit's 4 gates + cell; h is exchanged with the partner lane via shfl.
// Blocks of 64 -> 128 blocks -> <=1 block/SM, warps land on 2 SMSPs.
__global__ void __launch_bounds__(64, 1)
lstm_seq2_kernel(const int*   __restrict__ ids,
                 const float* __restrict__ E,
                 const float* __restrict__ W,
                 const float* __restrict__ U,
                 const float* __restrict__ bias,
                 float*       __restrict__ out)
{
    // Zt2[v][u] = float4 of gate preactivations {i,f,g,o} for unit u:
    //   gate column g = 2*j + u  (j = 0..3 over i,f,g,o)
    __shared__ float4 Zt2[VOCAB * 2];          // 9600 B

    const int tid  = threadIdx.x;
    const int u    = tid & 1;                  // hidden unit of this thread

    for (int idx = tid; idx < VOCAB * 2 * 4; idx += 64) {
        int v  = idx >> 3;
        int uu = (idx >> 2) & 1;
        int j  = idx & 3;
        int g  = 2 * j + uu;
        reinterpret_cast<float*>(Zt2)[ (v*2 + uu)*4 + j ] =
            fmaf(E[2*v], W[g], fmaf(E[2*v + 1], W[GG + g], bias[g]));
    }

    // Recurrent kernel columns for my unit's 4 gates
    float u0[4], u1[4];
#pragma unroll
    for (int j = 0; j < 4; j++) {
        int g = 2 * j + u;
        u0[j] = U[g];            // row h0
        u1[j] = U[GG + g];       // row h1
    }

    __syncthreads();

    const int row  = (blockIdx.x * 64 + tid) >> 1;   // 0..4095
    const int4*   idp  = reinterpret_cast<const int4*>(ids + (size_t)row * TT);
    float4*       outp = reinterpret_cast<float4*>(out + (size_t)row * TT * HID);

    float ha = 0.0f, hb = 0.0f;   // h of unit0 / unit1 (both lanes keep both)
    float c  = 0.0f;              // my unit's cell

    const bool even = (u == 0);

    for (int t4 = 0; t4 < TT / 4; t4++) {
        const int4 iv = idp[t4];                  // both lanes: same addr (broadcast)
        int idv[4] = { iv.x, iv.y, iv.z, iv.w };

        // Prefetch gate tables for all 4 steps (off the dependent chain)
        float4 zt[4];
#pragma unroll
        for (int k = 0; k < 4; k++) zt[k] = Zt2[idv[k] * 2 + u];

        float hbuf[8];

#pragma unroll
        for (int k = 0; k < 4; k++) {
            float zi = fmaf(hb, u1[0], fmaf(ha, u0[0], zt[k].x));
            float zf = fmaf(hb, u1[1], fmaf(ha, u0[1], zt[k].y));
            float zg = fmaf(hb, u1[2], fmaf(ha, u0[2], zt[k].z));
            float zo = fmaf(hb, u1[3], fmaf(ha, u0[3], zt[k].w));

            float ig = sig_f(zi);
            float fg = sig_f(zf);
            float gg = tanh_f(zg);
            float og = sig_f(zo);

            c = fmaf(fg, c, ig * gg);
            float hm   = og * tanh_f(c);
            float hoth = __shfl_xor_sync(0xffffffffu, hm, 1);

            ha = even ? hm   : hoth;
            hb = even ? hoth : hm;

            hbuf[2*k]   = ha;
            hbuf[2*k+1] = hb;
        }

        // 8 floats per 4 steps; lane pair splits the two float4 stores
        if (even)
            outp[t4*2 + 0] = make_float4(hbuf[0], hbuf[1], hbuf[2], hbuf[3]);
        else
            outp[t4*2 + 1] = make_float4(hbuf[4], hbuf[5], hbuf[6], hbuf[7]);
    }
}

extern "C" void kernel_launch(void* const* d_in, const int* in_sizes, int n_in,
                              void* d_out, int out_size)
{
    const int*   ids  = (const int*)  d_in[0];   // [B, T] int32
    const float* E    = (const float*)d_in[1];   // [300, 2]
    const float* W    = (const float*)d_in[2];   // [2, 8]
    const float* U    = (const float*)d_in[3];   // [2, 8]
    const float* bias = (const float*)d_in[4];   // [8]
    float*       out  = (float*)d_out;           // [B, T, 2]

    (void)in_sizes; (void)n_in; (void)out_size;

    lstm_seq2_kernel<<<(BB * 2) / 64, 64>>>(ids, E, W, U, bias, out);
}

// round 3
// speedup vs baseline: 1.7314x; 1.7172x over previous
#include <cuda_runtime.h>
#include <cstdint>

#define BB    4096
#define TT    2048
#define VOCAB 300
#define HID   2
#define GG    8

// log2(e) and 2*log2(e), negated (folded into the activation muls)
#define K1N  (-1.4426950408889634f)
#define K2N  (-2.8853900817779268f)

__device__ __forceinline__ float ex2f_(float x) {
    float r; asm("ex2.approx.ftz.f32 %0, %1;" : "=f"(r) : "f"(x)); return r;
}
__device__ __forceinline__ float rcpf_(float x) {
    float r; asm("rcp.approx.ftz.f32 %0, %1;" : "=f"(r) : "f"(x)); return r;
}
// sigmoid(x) = 1/(1+2^(-x*log2e)) : FMUL, EX2, FADD, RCP  (chain ~40)
__device__ __forceinline__ float sig_f(float x) {
    return rcpf_(1.0f + ex2f_(x * K1N));
}

// 2 threads per batch row (lane parity = hidden unit). h exchanged via shfl.
// ids software-pipelined 2 iterations deep; gate-table LDS prefetched 1 deep.
__global__ void __launch_bounds__(64, 1)
lstm_seq3_kernel(const int*   __restrict__ ids,
                 const float* __restrict__ E,
                 const float* __restrict__ W,
                 const float* __restrict__ U,
                 const float* __restrict__ bias,
                 float*       __restrict__ out)
{
    // Zt2[v*2+u] = {i,f,g,o} preactivations for token v, unit u
    __shared__ float4 Zt2[VOCAB * 2];

    const int tid = threadIdx.x;
    const int u   = tid & 1;

    for (int idx = tid; idx < VOCAB * 2 * 4; idx += 64) {
        int v  = idx >> 3;
        int uu = (idx >> 2) & 1;
        int j  = idx & 3;
        int g  = 2 * j + uu;                       // gate column
        reinterpret_cast<float*>(Zt2)[(v * 2 + uu) * 4 + j] =
            fmaf(E[2 * v], W[g], fmaf(E[2 * v + 1], W[GG + g], bias[g]));
    }

    // Recurrent coefficients, pre-swapped per lane so that:
    //   z = fma(h_other, cB, fma(h_mine, cA, zt))
    // cA multiplies MY unit's h, cB the partner's.
    float cA[4], cB[4];
#pragma unroll
    for (int j = 0; j < 4; j++) {
        int g = 2 * j + u;
        cA[j] = U[u * GG + g];           // row of my unit
        cB[j] = U[(1 - u) * GG + g];     // row of partner unit
    }

    __syncthreads();

    const int row = (blockIdx.x * 64 + tid) >> 1;
    const int4* idp  = reinterpret_cast<const int4*>(ids + (size_t)row * TT);
    float4*     outp = reinterpret_cast<float4*>(out + (size_t)row * TT * HID);

    const bool even = (u == 0);

    // ---- software pipeline prologue ----
    int4 ivA = idp[0];                    // ids for iter 0
    int4 ivB = idp[1];                    // ids for iter 1
    float4 ztc[4];                        // gate table for current iter
    {
        int ia[4] = { ivA.x, ivA.y, ivA.z, ivA.w };
#pragma unroll
        for (int k = 0; k < 4; k++) ztc[k] = Zt2[ia[k] * 2 + u];
    }

    float hm = 0.0f;   // my unit's h
    float ho = 0.0f;   // partner unit's h
    float c  = 0.0f;

#pragma unroll 2
    for (int t4 = 0; t4 < TT / 4; t4++) {
        // prefetch ids 2 iters ahead (covers ~577cyc DRAM under ~1150cyc compute)
        int nx = t4 + 2;  if (nx > TT / 4 - 1) nx = TT / 4 - 1;
        const int4 ivC = idp[nx];

        // prefetch gate table 1 iter ahead (LDS off the chain)
        float4 ztn[4];
        {
            int ib[4] = { ivB.x, ivB.y, ivB.z, ivB.w };
#pragma unroll
            for (int k = 0; k < 4; k++) ztn[k] = Zt2[ib[k] * 2 + u];
        }

        float hbuf[8];

#pragma unroll
        for (int k = 0; k < 4; k++) {
            // partial z with my own h first (ready before the shfl'd partner h)
            float zi = fmaf(hm, cA[0], ztc[k].x);
            float zf = fmaf(hm, cA[1], ztc[k].y);
            float zg = fmaf(hm, cA[2], ztc[k].z);
            float zo = fmaf(hm, cA[3], ztc[k].w);
            zi = fmaf(ho, cB[0], zi);
            zf = fmaf(ho, cB[1], zf);
            zg = fmaf(ho, cB[2], zg);
            zo = fmaf(ho, cB[3], zo);

            float ig = sig_f(zi);
            float fg = sig_f(zf);
            float og = sig_f(zo);
            // tanh(zg) = 2/(1+2^(-2 log2e zg)) - 1
            float rg = rcpf_(1.0f + ex2f_(zg * K2N));
            float gg = fmaf(2.0f, rg, -1.0f);

            c = fmaf(fg, c, ig * gg);

            // h = og * tanh(c) = fma(2og, rcp(1+e), -og); 2og off-chain
            float og2 = og + og;
            float rc  = rcpf_(1.0f + ex2f_(c * K2N));
            float hn  = fmaf(og2, rc, -og);

            float hx = __shfl_xor_sync(0xffffffffu, hn, 1);

            hbuf[2 * k]     = even ? hn : hx;   // unit0's h
            hbuf[2 * k + 1] = even ? hx : hn;   // unit1's h

            hm = hn;
            ho = hx;
        }

        if (even)
            outp[t4 * 2 + 0] = make_float4(hbuf[0], hbuf[1], hbuf[2], hbuf[3]);
        else
            outp[t4 * 2 + 1] = make_float4(hbuf[4], hbuf[5], hbuf[6], hbuf[7]);

        // rotate pipeline
#pragma unroll
        for (int k = 0; k < 4; k++) ztc[k] = ztn[k];
        ivB = ivC;
    }
}

extern "C" void kernel_launch(void* const* d_in, const int* in_sizes, int n_in,
                              void* d_out, int out_size)
{
    const int*   ids  = (const int*)  d_in[0];
    const float* E    = (const float*)d_in[1];
    const float* W    = (const float*)d_in[2];
    const float* U    = (const float*)d_in[3];
    const float* bias = (const float*)d_in[4];
    float*       out  = (float*)d_out;

    (void)in_sizes; (void)n_in; (void)out_size;

    lstm_seq3_kernel<<<(BB * 2) / 64, 64>>>(ids, E, W, U, bias, out);
}